// round 13
// baseline (speedup 1.0000x reference)
#include <cuda_runtime.h>
#include <cuda_fp16.h>
#include <mma.h>
#include <math.h>

using namespace nvcuda;

#define FULL 0xffffffffu

static const int NMAX = 50000;
static const int NPAD = 50048;          // 391 * 128
static const int CAP  = 192;            // bucket capacity (Poisson(32) tail ~1e-100)
static const long long EMAX = 1600000;

// ---------------- scratch (static __device__ — no allocation) ----------------
__device__ __align__(32) __half g_h1h[NPAD * 128];
__device__ __align__(32) __half g_l1h[NPAD * 128];
__device__ __align__(32) __half g_h2h[NPAD * 64];
__device__ __align__(16) float g_as1[NMAX * 4];
__device__ __align__(16) float g_ad1[NMAX * 4];
__device__ float g_as2[NMAX];
__device__ float g_ad2[NMAX];
__device__ int   g_cnt[NMAX];
__device__ int   g_srcs[NMAX * CAP];
__device__ int   g_is64;

// ---------------- init: zero counters + edge dtype detection ----------------
__global__ void init_k(const void* ei, int n, int* __restrict__ cnt) {
    int i = blockIdx.x * blockDim.x + threadIdx.x;
    if (i < n) cnt[i] = 0;
    if (blockIdx.x == 0 && threadIdx.x == 0) {
        const long long* p = (const long long*)ei;
        int ok = 1;
        for (int k = 0; k < 64; k++) {
            long long v = p[k];
            if (v < 0 || v >= (long long)n) { ok = 0; break; }
        }
        g_is64 = ok;
    }
}

__device__ __forceinline__ int edge_src(const void* ei, long long E, long long i) {
    return g_is64 ? (int)((const long long*)ei)[i] : ((const int*)ei)[i];
}
__device__ __forceinline__ int edge_dst(const void* ei, long long E, long long i) {
    return g_is64 ? (int)((const long long*)ei)[E + i] : ((const int*)ei)[E + i];
}

// ---------------- one-pass bucket scatter ----------------
__global__ void scat_k(const void* ei, long long E, int n, int* __restrict__ cnt,
                       int* __restrict__ srcs) {
    long long total = E + n;
    for (long long i = (long long)blockIdx.x * blockDim.x + threadIdx.x; i < total;
         i += (long long)gridDim.x * blockDim.x) {
        int s, d;
        if (i < E) { s = edge_src(ei, E, i); d = edge_dst(ei, E, i); }
        else { s = d = (int)(i - E); }
        int pos = atomicAdd(&cnt[d], 1);
        if (pos < CAP) srcs[d * CAP + pos] = s;
    }
}

// ---------------- GEMM1 (wmma) + fused alpha1 ----------------
__global__ __launch_bounds__(256)
void gemm1_k(const float* __restrict__ A, const float* __restrict__ W,
             const float* __restrict__ a_src, const float* __restrict__ a_dst,
             __half* __restrict__ Ch, float* __restrict__ asrc,
             float* __restrict__ adst, int n) {
    __shared__ __half As[2][128][48];
    __shared__ __half Bs[2][32][144];

    int tid = threadIdx.x;
    int wid = tid >> 5, lane = tid & 31;
    int wm = wid >> 2, wn = wid & 3;
    int row0 = blockIdx.x * 128;

    float4 va[4], vw[4];
    auto fetch = [&](int kc) {
#pragma unroll
        for (int q = 0; q < 4; q++) {
            int f = tid + q * 256;
            int r = f >> 3, c4 = f & 7;
            int gr = row0 + r;
            va[q] = (gr < n) ? *reinterpret_cast<const float4*>(&A[(size_t)gr * 128 + kc + c4 * 4])
                             : make_float4(0.f, 0.f, 0.f, 0.f);
        }
#pragma unroll
        for (int q = 0; q < 4; q++) {
            int f = tid + q * 256;
            int r = f >> 5, c4 = f & 31;
            vw[q] = *reinterpret_cast<const float4*>(&W[(size_t)(kc + r) * 128 + c4 * 4]);
        }
    };
    auto store = [&](int b) {
#pragma unroll
        for (int q = 0; q < 4; q++) {
            int f = tid + q * 256;
            int r = f >> 3, c = (f & 7) * 4;
            *reinterpret_cast<__half2*>(&As[b][r][c])     = __floats2half2_rn(va[q].x, va[q].y);
            *reinterpret_cast<__half2*>(&As[b][r][c + 2]) = __floats2half2_rn(va[q].z, va[q].w);
        }
#pragma unroll
        for (int q = 0; q < 4; q++) {
            int f = tid + q * 256;
            int r = f >> 5, c = (f & 31) * 4;
            *reinterpret_cast<__half2*>(&Bs[b][r][c])     = __floats2half2_rn(vw[q].x, vw[q].y);
            *reinterpret_cast<__half2*>(&Bs[b][r][c + 2]) = __floats2half2_rn(vw[q].z, vw[q].w);
        }
    };

    wmma::fragment<wmma::accumulator, 16, 16, 16, float> cf[4][2];
#pragma unroll
    for (int i = 0; i < 4; i++)
#pragma unroll
        for (int j = 0; j < 2; j++) wmma::fill_fragment(cf[i][j], 0.f);

    fetch(0); store(0); __syncthreads();

#pragma unroll
    for (int it = 0; it < 4; it++) {
        int b = it & 1;
        if (it < 3) fetch((it + 1) * 32);
#pragma unroll
        for (int kk = 0; kk < 32; kk += 16) {
            wmma::fragment<wmma::matrix_a, 16, 16, 16, __half, wmma::row_major> af[4];
            wmma::fragment<wmma::matrix_b, 16, 16, 16, __half, wmma::row_major> bf[2];
#pragma unroll
            for (int i = 0; i < 4; i++)
                wmma::load_matrix_sync(af[i], &As[b][wm * 64 + i * 16][kk], 48);
#pragma unroll
            for (int j = 0; j < 2; j++)
                wmma::load_matrix_sync(bf[j], &Bs[b][kk][wn * 32 + j * 16], 144);
#pragma unroll
            for (int i = 0; i < 4; i++)
#pragma unroll
                for (int j = 0; j < 2; j++)
                    wmma::mma_sync(cf[i][j], af[i], bf[j], cf[i][j]);
        }
        if (it < 3) store(b ^ 1);
        __syncthreads();
    }

    float (*cs)[16][20] = reinterpret_cast<float (*)[16][20]>(&As[0][0][0]);
    int r = lane >> 1, hh = lane & 1;
#pragma unroll
    for (int i = 0; i < 4; i++) {
        float asum = 0.f, dsum = 0.f;
#pragma unroll
        for (int j = 0; j < 2; j++) {
            wmma::store_matrix_sync(&cs[wid][0][0], cf[i][j], 20, wmma::mem_row_major);
            __syncwarp();
            const float* rp = &cs[wid][r][hh * 8];
            __half2 o[4];
#pragma unroll
            for (int t = 0; t < 4; t++) {
                float w0 = rp[2 * t], w1 = rp[2 * t + 1];
                o[t] = __floats2half2_rn(w0, w1);
                int c = wn * 32 + j * 16 + hh * 8 + 2 * t;
                asum += w0 * __ldg(&a_src[c]) + w1 * __ldg(&a_src[c + 1]);
                dsum += w0 * __ldg(&a_dst[c]) + w1 * __ldg(&a_dst[c + 1]);
            }
            *reinterpret_cast<uint4*>(
                &Ch[(size_t)(row0 + wm * 64 + i * 16 + r) * 128 + wn * 32 + j * 16 + hh * 8]) =
                *reinterpret_cast<uint4*>(o);
            __syncwarp();
        }
        asum += __shfl_xor_sync(FULL, asum, 1);
        dsum += __shfl_xor_sync(FULL, dsum, 1);
        int gr = row0 + wm * 64 + i * 16 + r;
        if (hh == 0 && gr < n) {
            asrc[gr * 4 + wn] = asum;
            adst[gr * 4 + wn] = dsum;
        }
    }
}

// ---------------- GEMM2 (wmma) + fused alpha2 ----------------
__global__ __launch_bounds__(256)
void gemm2_k(const __half* __restrict__ Ah, const float* __restrict__ W,
             const float* __restrict__ a_src, const float* __restrict__ a_dst,
             __half* __restrict__ Ch, float* __restrict__ asrc,
             float* __restrict__ adst, int n) {
    __shared__ __half As[2][128][48];
    __shared__ __half Bs[2][32][80];
    __shared__ float spa[128][2], spd[128][2];

    int tid = threadIdx.x;
    int wid = tid >> 5, lane = tid & 31;
    int wm = wid >> 1, wn = wid & 1;
    int row0 = blockIdx.x * 128;

    uint2 va[4]; float4 vw[2];
    auto fetch = [&](int kc) {
#pragma unroll
        for (int q = 0; q < 4; q++) {
            int f = tid + q * 256;
            int r = f >> 3, c4 = f & 7;
            int gr = row0 + r;
            va[q] = (gr < n) ? *reinterpret_cast<const uint2*>(&Ah[(size_t)gr * 128 + kc + c4 * 4])
                             : make_uint2(0u, 0u);
        }
#pragma unroll
        for (int q = 0; q < 2; q++) {
            int f = tid + q * 256;
            int r = f >> 4, c4 = f & 15;
            vw[q] = *reinterpret_cast<const float4*>(&W[(size_t)(kc + r) * 64 + c4 * 4]);
        }
    };
    auto store = [&](int b) {
#pragma unroll
        for (int q = 0; q < 4; q++) {
            int f = tid + q * 256;
            int r = f >> 3, c = (f & 7) * 4;
            *reinterpret_cast<uint2*>(&As[b][r][c]) = va[q];
        }
#pragma unroll
        for (int q = 0; q < 2; q++) {
            int f = tid + q * 256;
            int r = f >> 4, c = (f & 15) * 4;
            *reinterpret_cast<__half2*>(&Bs[b][r][c])     = __floats2half2_rn(vw[q].x, vw[q].y);
            *reinterpret_cast<__half2*>(&Bs[b][r][c + 2]) = __floats2half2_rn(vw[q].z, vw[q].w);
        }
    };

    wmma::fragment<wmma::accumulator, 16, 16, 16, float> cf[2][2];
#pragma unroll
    for (int i = 0; i < 2; i++)
#pragma unroll
        for (int j = 0; j < 2; j++) wmma::fill_fragment(cf[i][j], 0.f);

    fetch(0); store(0); __syncthreads();

#pragma unroll
    for (int it = 0; it < 4; it++) {
        int b = it & 1;
        if (it < 3) fetch((it + 1) * 32);
#pragma unroll
        for (int kk = 0; kk < 32; kk += 16) {
            wmma::fragment<wmma::matrix_a, 16, 16, 16, __half, wmma::row_major> af[2];
            wmma::fragment<wmma::matrix_b, 16, 16, 16, __half, wmma::row_major> bf[2];
#pragma unroll
            for (int i = 0; i < 2; i++)
                wmma::load_matrix_sync(af[i], &As[b][wm * 32 + i * 16][kk], 48);
#pragma unroll
            for (int j = 0; j < 2; j++)
                wmma::load_matrix_sync(bf[j], &Bs[b][kk][wn * 32 + j * 16], 80);
#pragma unroll
            for (int i = 0; i < 2; i++)
#pragma unroll
                for (int j = 0; j < 2; j++)
                    wmma::mma_sync(cf[i][j], af[i], bf[j], cf[i][j]);
        }
        if (it < 3) store(b ^ 1);
        __syncthreads();
    }

    float (*cs)[16][20] = reinterpret_cast<float (*)[16][20]>(&As[0][0][0]);
    int r = lane >> 1, hh = lane & 1;
#pragma unroll
    for (int i = 0; i < 2; i++) {
        float asum = 0.f, dsum = 0.f;
#pragma unroll
        for (int j = 0; j < 2; j++) {
            wmma::store_matrix_sync(&cs[wid][0][0], cf[i][j], 20, wmma::mem_row_major);
            __syncwarp();
            const float* rp = &cs[wid][r][hh * 8];
            __half2 o[4];
#pragma unroll
            for (int t = 0; t < 4; t++) {
                float w0 = rp[2 * t], w1 = rp[2 * t + 1];
                o[t] = __floats2half2_rn(w0, w1);
                int c = wn * 32 + j * 16 + hh * 8 + 2 * t;
                asum += w0 * __ldg(&a_src[c]) + w1 * __ldg(&a_src[c + 1]);
                dsum += w0 * __ldg(&a_dst[c]) + w1 * __ldg(&a_dst[c + 1]);
            }
            *reinterpret_cast<uint4*>(
                &Ch[(size_t)(row0 + wm * 32 + i * 16 + r) * 64 + wn * 32 + j * 16 + hh * 8]) =
                *reinterpret_cast<uint4*>(o);
            __syncwarp();
        }
        asum += __shfl_xor_sync(FULL, asum, 1);
        dsum += __shfl_xor_sync(FULL, dsum, 1);
        int lr = wm * 32 + i * 16 + r;
        if (hh == 0) { spa[lr][wn] = asum; spd[lr][wn] = dsum; }
    }
    __syncthreads();
    if (tid < 128) {
        int gr = row0 + tid;
        if (gr < n) {
            asrc[gr] = spa[tid][0] + spa[tid][1];
            adst[gr] = spd[tid][0] + spd[tid][1];
        }
    }
}

// ---------------- layer1 aggregation: HMMA (m8n32k16) per 16-edge step ----------
// Per warp (one dst node at a time):
//   A tile [8][24] half: rows 0-3 = q per head (half), rows 4-7 zero.
//   B tiles: gathered h rows, Hg[16][136] half (16 edges x 128 ch, pad 8).
//   D[t] (8x32 fp32 fragment) accumulates head-t weighting of channels [32t,32t+32).
//   Epilogue: store D tiles to smem, read row t of tile t, normalize, bias, relu.
__global__ __launch_bounds__(256)
void agg1_k(const __half* __restrict__ hfeat, const float* __restrict__ asrc,
            const float* __restrict__ adst, const int* __restrict__ cnt,
            const int* __restrict__ srcs, const float* __restrict__ b1,
            __half* __restrict__ out, int n) {
    __shared__ __align__(16) __half Hg[8][16][136];   // 34816 B (also reused as fp32 D staging)
    __shared__ __align__(16) __half At[8][8][24];     // 3072 B
    __shared__ int Ssm[8][16];                        // 512 B

    const int warp0 = (blockIdx.x * blockDim.x + threadIdx.x) >> 5;
    const int wl    = threadIdx.x >> 5;
    const int lane  = threadIdx.x & 31;
    const int nw    = (gridDim.x * blockDim.x) >> 5;
    const int hsel  = lane >> 3;                      // head of this lane's 4 out channels

    // zero A tile once (rows 4-7 stay zero forever; rows 0-3 rewritten each step)
    {
        unsigned* az = reinterpret_cast<unsigned*>(&At[wl][0][0]);
        for (int i = lane; i < 8 * 24 / 2; i += 32) az[i] = 0u;
    }
    float4 bb = reinterpret_cast<const float4*>(b1)[lane];
    __syncwarp();

    for (int v = warp0; v < n; v += nw) {
        int deg = min(cnt[v], CAP);
        int s0 = v * CAP;
        float4 ad = reinterpret_cast<const float4*>(adst)[v];

        wmma::fragment<wmma::accumulator, 8, 32, 16, float> D[4];
#pragma unroll
        for (int t = 0; t < 4; t++) wmma::fill_fragment(D[t], 0.f);
        float4 den4 = {0.f, 0.f, 0.f, 0.f};

        for (int base = 0; base < deg; base += 16) {
            __syncwarp();                 // prior MMA reads done before overwrite
            if (lane < 16) {
                int i = base + lane;
                int src = 0;
                float q0 = 0.f, q1 = 0.f, q2 = 0.f, q3 = 0.f;
                if (i < deg) {
                    src = srcs[s0 + i];
                    float4 as = reinterpret_cast<const float4*>(asrc)[src];
                    float e;
                    e = as.x + ad.x; e = e > 0.f ? e : 0.2f * e; q0 = __expf(e);
                    e = as.y + ad.y; e = e > 0.f ? e : 0.2f * e; q1 = __expf(e);
                    e = as.z + ad.z; e = e > 0.f ? e : 0.2f * e; q2 = __expf(e);
                    e = as.w + ad.w; e = e > 0.f ? e : 0.2f * e; q3 = __expf(e);
                }
                Ssm[wl][lane] = src;
                __half h0 = __float2half_rn(q0), h1 = __float2half_rn(q1);
                __half h2 = __float2half_rn(q2), h3 = __float2half_rn(q3);
                At[wl][0][lane] = h0; At[wl][1][lane] = h1;
                At[wl][2][lane] = h2; At[wl][3][lane] = h3;
                // den from the same half-rounded q (consistent with MMA numerator)
                den4.x += __half2float(h0); den4.y += __half2float(h1);
                den4.z += __half2float(h2); den4.w += __half2float(h3);
            }
            __syncwarp();
            // gather: lane covers half a row. row = lane>>1, half = lane&1 (128 B)
            {
                int sr = Ssm[wl][lane >> 1];
                const uint4* gp = reinterpret_cast<const uint4*>(
                    hfeat + (size_t)sr * 128 + (lane & 1) * 64);
                uint4* sp = reinterpret_cast<uint4*>(&Hg[wl][lane >> 1][(lane & 1) * 64]);
#pragma unroll
                for (int t = 0; t < 8; t++) sp[t] = gp[t];
            }
            __syncwarp();
            // MMA: A (8x16) x B tiles (16x32)
            wmma::fragment<wmma::matrix_a, 8, 32, 16, __half, wmma::row_major> af;
            wmma::load_matrix_sync(af, &At[wl][0][0], 24);
#pragma unroll
            for (int t = 0; t < 4; t++) {
                wmma::fragment<wmma::matrix_b, 8, 32, 16, __half, wmma::row_major> bf;
                wmma::load_matrix_sync(bf, &Hg[wl][0][t * 32], 136);
                wmma::mma_sync(D[t], af, bf, D[t]);
            }
        }

        // epilogue: stage D tiles as fp32 into Hg area, extract row t of tile t
        __syncwarp();
        float* Dst = reinterpret_cast<float*>(&Hg[wl][0][0]);   // 4 tiles x 8x32 fp32 = 4096 B
#pragma unroll
        for (int t = 0; t < 4; t++)
            wmma::store_matrix_sync(Dst + t * 256, D[t], 32, wmma::mem_row_major);
        // reduce den across lanes (lanes >=16 hold 0)
#pragma unroll
        for (int o = 16; o; o >>= 1) {
            den4.x += __shfl_xor_sync(FULL, den4.x, o);
            den4.y += __shfl_xor_sync(FULL, den4.y, o);
            den4.z += __shfl_xor_sync(FULL, den4.z, o);
            den4.w += __shfl_xor_sync(FULL, den4.w, o);
        }
        __syncwarp();
        float den = (hsel == 0) ? den4.x : (hsel == 1) ? den4.y
                  : (hsel == 2) ? den4.z : den4.w;
        float rd = 1.f / (den + 1e-16f);
        // lane's 4 channels: [4*lane, 4*lane+4) -> tile hsel, row hsel, cols (4*lane)&31
        float4 acc = *reinterpret_cast<const float4*>(
            Dst + hsel * 256 + hsel * 32 + ((4 * lane) & 31));
        uint2 ov;
        *reinterpret_cast<__half2*>(&ov.x) =
            __floats2half2_rn(fmaxf(acc.x * rd + bb.x, 0.f), fmaxf(acc.y * rd + bb.y, 0.f));
        *reinterpret_cast<__half2*>(&ov.y) =
            __floats2half2_rn(fmaxf(acc.z * rd + bb.z, 0.f), fmaxf(acc.w * rd + bb.w, 0.f));
        reinterpret_cast<uint2*>(out + (size_t)v * 128)[lane] = ov;
        __syncwarp();                    // Dst reads done before next node's gather
    }
}

// ---------------- layer2 aggregation (1 head, 64 ch), 8-wide batched ----------------
__global__ __launch_bounds__(256)
void agg2_k(const __half* __restrict__ hfeat, const float* __restrict__ asrc,
            const float* __restrict__ adst, const int* __restrict__ cnt,
            const int* __restrict__ srcs, const float* __restrict__ b2,
            float* __restrict__ out, int n) {
    __shared__ float2 sq[8][32];
    const __half2* hf2 = reinterpret_cast<const __half2*>(hfeat);

    int warp = (blockIdx.x * blockDim.x + threadIdx.x) >> 5;
    int wl   = (threadIdx.x >> 5);
    int lane = threadIdx.x & 31;
    int nw = (gridDim.x * blockDim.x) >> 5;
    float2 b = reinterpret_cast<const float2*>(b2)[lane];

    for (int v = warp; v < n; v += nw) {
        int deg = min(cnt[v], CAP);
        int s0 = v * CAP;
        float ad = adst[v];
        float den = 0.f;
        float2 a = {0.f, 0.f};

        for (int base = 0; base < deg; base += 32) {
            int i = base + lane;
            float p = 0.f;
            int src = 0;
            if (i < deg) {
                src = srcs[s0 + i];
                float e = asrc[src] + ad;
                e = e > 0.f ? e : 0.2f * e;
                p = __expf(e);
            }
            __syncwarp();
            sq[wl][lane] = make_float2(p, __int_as_float(src));
            __syncwarp();
            int c = min(32, deg - base);
            int j = 0;
            for (; j + 8 <= c; j += 8) {
                float qv[8]; int sv[8];
#pragma unroll
                for (int t = 0; t < 8; t++) {
                    float2 tt = sq[wl][j + t];
                    qv[t] = tt.x;
                    sv[t] = __float_as_int(tt.y);
                }
                __half2 hv[8];
#pragma unroll
                for (int t = 0; t < 8; t++)
                    hv[t] = hf2[(size_t)sv[t] * 32 + lane];
#pragma unroll
                for (int t = 0; t < 8; t++) {
                    float2 f = __half22float2(hv[t]);
                    a.x = fmaf(qv[t], f.x, a.x);
                    a.y = fmaf(qv[t], f.y, a.y);
                    den += qv[t];
                }
            }
            for (; j < c; j++) {
                float2 t = sq[wl][j];
                float q = t.x;
                int  sj = __float_as_int(t.y);
                float2 f = __half22float2(hf2[(size_t)sj * 32 + lane]);
                a.x = fmaf(q, f.x, a.x);
                a.y = fmaf(q, f.y, a.y);
                den += q;
            }
        }
        float rd = 1.f / (den + 1e-16f);
        float2 o;
        o.x = a.x * rd + b.x;
        o.y = a.y * rd + b.y;
        reinterpret_cast<float2*>(out + (size_t)v * 64)[lane] = o;
    }
}

// ---------------- launch ----------------
extern "C" void kernel_launch(void* const* d_in, const int* in_sizes, int n_in,
                              void* d_out, int out_size) {
    const float* x   = (const float*)d_in[0];
    const void*  ei  = d_in[1];
    const float* W1  = (const float*)d_in[2];
    const float* as1 = (const float*)d_in[3];
    const float* ad1 = (const float*)d_in[4];
    const float* b1  = (const float*)d_in[5];
    const float* W2  = (const float*)d_in[6];
    const float* as2 = (const float*)d_in[7];
    const float* ad2 = (const float*)d_in[8];
    const float* b2  = (const float*)d_in[9];
    float* out = (float*)d_out;

    int n = in_sizes[0] / 128;           // 50000
    long long E = in_sizes[1] / 2;       // 1600000

    __half *p_h1h, *p_l1h, *p_h2h;
    float *p_as1, *p_ad1, *p_as2, *p_ad2;
    int *p_cnt, *p_srcs;
    cudaGetSymbolAddress((void**)&p_h1h, g_h1h);
    cudaGetSymbolAddress((void**)&p_l1h, g_l1h);
    cudaGetSymbolAddress((void**)&p_h2h, g_h2h);
    cudaGetSymbolAddress((void**)&p_as1, g_as1);
    cudaGetSymbolAddress((void**)&p_ad1, g_ad1);
    cudaGetSymbolAddress((void**)&p_as2, g_as2);
    cudaGetSymbolAddress((void**)&p_ad2, g_ad2);
    cudaGetSymbolAddress((void**)&p_cnt, g_cnt);
    cudaGetSymbolAddress((void**)&p_srcs, g_srcs);

    int gemm_blocks = (n + 127) / 128;
    int warp_blocks = (n * 32 + 255) / 256;

    cudaStream_t s2;
    cudaEvent_t ev1, ev2;
    cudaStreamCreateWithFlags(&s2, cudaStreamNonBlocking);
    cudaEventCreateWithFlags(&ev1, cudaEventDisableTiming);
    cudaEventCreateWithFlags(&ev2, cudaEventDisableTiming);

    cudaEventRecord(ev1, 0);
    cudaStreamWaitEvent(s2, ev1, 0);

    init_k<<<(n + 255) / 256, 256, 0, s2>>>(ei, n, p_cnt);
    scat_k<<<2048, 256, 0, s2>>>(ei, E, n, p_cnt, p_srcs);
    cudaEventRecord(ev2, s2);

    gemm1_k<<<gemm_blocks, 256>>>(x, W1, as1, ad1, p_h1h, p_as1, p_ad1, n);

    cudaStreamWaitEvent(0, ev2, 0);
    agg1_k<<<warp_blocks, 256>>>(p_h1h, p_as1, p_ad1, p_cnt, p_srcs, b1, p_l1h, n);
    gemm2_k<<<gemm_blocks, 256>>>(p_l1h, W2, as2, ad2, p_h2h, p_as2, p_ad2, n);
    agg2_k<<<warp_blocks, 256>>>(p_h2h, p_as2, p_ad2, p_cnt, p_srcs, b2, out, n);
}

// round 14
// speedup vs baseline: 1.6990x; 1.6990x over previous
#include <cuda_runtime.h>
#include <cuda_fp16.h>
#include <mma.h>
#include <math.h>

using namespace nvcuda;

#define FULL 0xffffffffu

static const int NMAX = 50000;
static const int NPAD = 50048;          // 391 * 128
static const int CAP  = 192;            // bucket capacity (Poisson(32) tail ~1e-100)
static const long long EMAX = 1600000;

// ---------------- scratch (static __device__ — no allocation) ----------------
__device__ __align__(32) __half g_h1h[NPAD * 128];
__device__ __align__(32) __half g_l1h[NPAD * 128];
__device__ __align__(32) __half g_h2h[NPAD * 64];
__device__ __align__(16) float g_as1[NMAX * 4];
__device__ __align__(16) float g_ad1[NMAX * 4];
__device__ float g_as2[NMAX];
__device__ float g_ad2[NMAX];
__device__ int   g_cnt[NMAX];
__device__ int   g_srcs[NMAX * CAP];
__device__ int   g_is64;

// ---------------- init: zero counters + edge dtype detection ----------------
__global__ void init_k(const void* ei, int n, int* __restrict__ cnt) {
    int i = blockIdx.x * blockDim.x + threadIdx.x;
    if (i < n) cnt[i] = 0;
    if (blockIdx.x == 0 && threadIdx.x == 0) {
        const long long* p = (const long long*)ei;
        int ok = 1;
        for (int k = 0; k < 64; k++) {
            long long v = p[k];
            if (v < 0 || v >= (long long)n) { ok = 0; break; }
        }
        g_is64 = ok;
    }
}

__device__ __forceinline__ int edge_src(const void* ei, long long E, long long i) {
    return g_is64 ? (int)((const long long*)ei)[i] : ((const int*)ei)[i];
}
__device__ __forceinline__ int edge_dst(const void* ei, long long E, long long i) {
    return g_is64 ? (int)((const long long*)ei)[E + i] : ((const int*)ei)[E + i];
}

// ---------------- one-pass bucket scatter ----------------
__global__ void scat_k(const void* ei, long long E, int n, int* __restrict__ cnt,
                       int* __restrict__ srcs) {
    long long total = E + n;
    for (long long i = (long long)blockIdx.x * blockDim.x + threadIdx.x; i < total;
         i += (long long)gridDim.x * blockDim.x) {
        int s, d;
        if (i < E) { s = edge_src(ei, E, i); d = edge_dst(ei, E, i); }
        else { s = d = (int)(i - E); }
        int pos = atomicAdd(&cnt[d], 1);
        if (pos < CAP) srcs[d * CAP + pos] = s;
    }
}

// ---------------- GEMM1 (wmma) + fused alpha1 ----------------
__global__ __launch_bounds__(256)
void gemm1_k(const float* __restrict__ A, const float* __restrict__ W,
             const float* __restrict__ a_src, const float* __restrict__ a_dst,
             __half* __restrict__ Ch, float* __restrict__ asrc,
             float* __restrict__ adst, int n) {
    __shared__ __half As[2][128][48];
    __shared__ __half Bs[2][32][144];

    int tid = threadIdx.x;
    int wid = tid >> 5, lane = tid & 31;
    int wm = wid >> 2, wn = wid & 3;
    int row0 = blockIdx.x * 128;

    float4 va[4], vw[4];
    auto fetch = [&](int kc) {
#pragma unroll
        for (int q = 0; q < 4; q++) {
            int f = tid + q * 256;
            int r = f >> 3, c4 = f & 7;
            int gr = row0 + r;
            va[q] = (gr < n) ? *reinterpret_cast<const float4*>(&A[(size_t)gr * 128 + kc + c4 * 4])
                             : make_float4(0.f, 0.f, 0.f, 0.f);
        }
#pragma unroll
        for (int q = 0; q < 4; q++) {
            int f = tid + q * 256;
            int r = f >> 5, c4 = f & 31;
            vw[q] = *reinterpret_cast<const float4*>(&W[(size_t)(kc + r) * 128 + c4 * 4]);
        }
    };
    auto store = [&](int b) {
#pragma unroll
        for (int q = 0; q < 4; q++) {
            int f = tid + q * 256;
            int r = f >> 3, c = (f & 7) * 4;
            *reinterpret_cast<__half2*>(&As[b][r][c])     = __floats2half2_rn(va[q].x, va[q].y);
            *reinterpret_cast<__half2*>(&As[b][r][c + 2]) = __floats2half2_rn(va[q].z, va[q].w);
        }
#pragma unroll
        for (int q = 0; q < 4; q++) {
            int f = tid + q * 256;
            int r = f >> 5, c = (f & 31) * 4;
            *reinterpret_cast<__half2*>(&Bs[b][r][c])     = __floats2half2_rn(vw[q].x, vw[q].y);
            *reinterpret_cast<__half2*>(&Bs[b][r][c + 2]) = __floats2half2_rn(vw[q].z, vw[q].w);
        }
    };

    wmma::fragment<wmma::accumulator, 16, 16, 16, float> cf[4][2];
#pragma unroll
    for (int i = 0; i < 4; i++)
#pragma unroll
        for (int j = 0; j < 2; j++) wmma::fill_fragment(cf[i][j], 0.f);

    fetch(0); store(0); __syncthreads();

#pragma unroll
    for (int it = 0; it < 4; it++) {
        int b = it & 1;
        if (it < 3) fetch((it + 1) * 32);
#pragma unroll
        for (int kk = 0; kk < 32; kk += 16) {
            wmma::fragment<wmma::matrix_a, 16, 16, 16, __half, wmma::row_major> af[4];
            wmma::fragment<wmma::matrix_b, 16, 16, 16, __half, wmma::row_major> bf[2];
#pragma unroll
            for (int i = 0; i < 4; i++)
                wmma::load_matrix_sync(af[i], &As[b][wm * 64 + i * 16][kk], 48);
#pragma unroll
            for (int j = 0; j < 2; j++)
                wmma::load_matrix_sync(bf[j], &Bs[b][kk][wn * 32 + j * 16], 144);
#pragma unroll
            for (int i = 0; i < 4; i++)
#pragma unroll
                for (int j = 0; j < 2; j++)
                    wmma::mma_sync(cf[i][j], af[i], bf[j], cf[i][j]);
        }
        if (it < 3) store(b ^ 1);
        __syncthreads();
    }

    float (*cs)[16][20] = reinterpret_cast<float (*)[16][20]>(&As[0][0][0]);
    int r = lane >> 1, hh = lane & 1;
#pragma unroll
    for (int i = 0; i < 4; i++) {
        float asum = 0.f, dsum = 0.f;
#pragma unroll
        for (int j = 0; j < 2; j++) {
            wmma::store_matrix_sync(&cs[wid][0][0], cf[i][j], 20, wmma::mem_row_major);
            __syncwarp();
            const float* rp = &cs[wid][r][hh * 8];
            __half2 o[4];
#pragma unroll
            for (int t = 0; t < 4; t++) {
                float w0 = rp[2 * t], w1 = rp[2 * t + 1];
                o[t] = __floats2half2_rn(w0, w1);
                int c = wn * 32 + j * 16 + hh * 8 + 2 * t;
                asum += w0 * __ldg(&a_src[c]) + w1 * __ldg(&a_src[c + 1]);
                dsum += w0 * __ldg(&a_dst[c]) + w1 * __ldg(&a_dst[c + 1]);
            }
            *reinterpret_cast<uint4*>(
                &Ch[(size_t)(row0 + wm * 64 + i * 16 + r) * 128 + wn * 32 + j * 16 + hh * 8]) =
                *reinterpret_cast<uint4*>(o);
            __syncwarp();
        }
        asum += __shfl_xor_sync(FULL, asum, 1);
        dsum += __shfl_xor_sync(FULL, dsum, 1);
        int gr = row0 + wm * 64 + i * 16 + r;
        if (hh == 0 && gr < n) {
            asrc[gr * 4 + wn] = asum;
            adst[gr * 4 + wn] = dsum;
        }
    }
}

// ---------------- GEMM2 (wmma) + fused alpha2 (row-chunked) ----------------
__global__ __launch_bounds__(256)
void gemm2_k(const __half* __restrict__ Ah, const float* __restrict__ W,
             const float* __restrict__ a_src, const float* __restrict__ a_dst,
             __half* __restrict__ Ch, float* __restrict__ asrc,
             float* __restrict__ adst, int n, int rowbase) {
    __shared__ __half As[2][128][48];
    __shared__ __half Bs[2][32][80];
    __shared__ float spa[128][2], spd[128][2];

    int tid = threadIdx.x;
    int wid = tid >> 5, lane = tid & 31;
    int wm = wid >> 1, wn = wid & 1;
    int row0 = rowbase + blockIdx.x * 128;

    uint2 va[4]; float4 vw[2];
    auto fetch = [&](int kc) {
#pragma unroll
        for (int q = 0; q < 4; q++) {
            int f = tid + q * 256;
            int r = f >> 3, c4 = f & 7;
            int gr = row0 + r;
            va[q] = (gr < n) ? *reinterpret_cast<const uint2*>(&Ah[(size_t)gr * 128 + kc + c4 * 4])
                             : make_uint2(0u, 0u);
        }
#pragma unroll
        for (int q = 0; q < 2; q++) {
            int f = tid + q * 256;
            int r = f >> 4, c4 = f & 15;
            vw[q] = *reinterpret_cast<const float4*>(&W[(size_t)(kc + r) * 64 + c4 * 4]);
        }
    };
    auto store = [&](int b) {
#pragma unroll
        for (int q = 0; q < 4; q++) {
            int f = tid + q * 256;
            int r = f >> 3, c = (f & 7) * 4;
            *reinterpret_cast<uint2*>(&As[b][r][c]) = va[q];
        }
#pragma unroll
        for (int q = 0; q < 2; q++) {
            int f = tid + q * 256;
            int r = f >> 4, c = (f & 15) * 4;
            *reinterpret_cast<__half2*>(&Bs[b][r][c])     = __floats2half2_rn(vw[q].x, vw[q].y);
            *reinterpret_cast<__half2*>(&Bs[b][r][c + 2]) = __floats2half2_rn(vw[q].z, vw[q].w);
        }
    };

    wmma::fragment<wmma::accumulator, 16, 16, 16, float> cf[2][2];
#pragma unroll
    for (int i = 0; i < 2; i++)
#pragma unroll
        for (int j = 0; j < 2; j++) wmma::fill_fragment(cf[i][j], 0.f);

    fetch(0); store(0); __syncthreads();

#pragma unroll
    for (int it = 0; it < 4; it++) {
        int b = it & 1;
        if (it < 3) fetch((it + 1) * 32);
#pragma unroll
        for (int kk = 0; kk < 32; kk += 16) {
            wmma::fragment<wmma::matrix_a, 16, 16, 16, __half, wmma::row_major> af[2];
            wmma::fragment<wmma::matrix_b, 16, 16, 16, __half, wmma::row_major> bf[2];
#pragma unroll
            for (int i = 0; i < 2; i++)
                wmma::load_matrix_sync(af[i], &As[b][wm * 32 + i * 16][kk], 48);
#pragma unroll
            for (int j = 0; j < 2; j++)
                wmma::load_matrix_sync(bf[j], &Bs[b][kk][wn * 32 + j * 16], 80);
#pragma unroll
            for (int i = 0; i < 2; i++)
#pragma unroll
                for (int j = 0; j < 2; j++)
                    wmma::mma_sync(cf[i][j], af[i], bf[j], cf[i][j]);
        }
        if (it < 3) store(b ^ 1);
        __syncthreads();
    }

    float (*cs)[16][20] = reinterpret_cast<float (*)[16][20]>(&As[0][0][0]);
    int r = lane >> 1, hh = lane & 1;
#pragma unroll
    for (int i = 0; i < 2; i++) {
        float asum = 0.f, dsum = 0.f;
#pragma unroll
        for (int j = 0; j < 2; j++) {
            wmma::store_matrix_sync(&cs[wid][0][0], cf[i][j], 20, wmma::mem_row_major);
            __syncwarp();
            const float* rp = &cs[wid][r][hh * 8];
            __half2 o[4];
#pragma unroll
            for (int t = 0; t < 4; t++) {
                float w0 = rp[2 * t], w1 = rp[2 * t + 1];
                o[t] = __floats2half2_rn(w0, w1);
                int c = wn * 32 + j * 16 + hh * 8 + 2 * t;
                asum += w0 * __ldg(&a_src[c]) + w1 * __ldg(&a_src[c + 1]);
                dsum += w0 * __ldg(&a_dst[c]) + w1 * __ldg(&a_dst[c + 1]);
            }
            *reinterpret_cast<uint4*>(
                &Ch[(size_t)(row0 + wm * 32 + i * 16 + r) * 64 + wn * 32 + j * 16 + hh * 8]) =
                *reinterpret_cast<uint4*>(o);
            __syncwarp();
        }
        asum += __shfl_xor_sync(FULL, asum, 1);
        dsum += __shfl_xor_sync(FULL, dsum, 1);
        int lr = wm * 32 + i * 16 + r;
        if (hh == 0) { spa[lr][wn] = asum; spd[lr][wn] = dsum; }
    }
    __syncthreads();
    if (tid < 128) {
        int gr = row0 + tid;
        if (gr < n) {
            asrc[gr] = spa[tid][0] + spa[tid][1];
            adst[gr] = spd[tid][0] + spd[tid][1];
        }
    }
}

// ---------------- layer1 aggregation: warp per dst, vectorized staging ----------
// q transposed by head with row stride 40 floats (160 B): 16B-aligned and
// 40h mod 32 = 8h -> the four 8-lane head groups read DISJOINT bank quadruples
// (conflict-free LDS.128). srcs read as int4 broadcast. 8-wide batched gathers.
__global__ __launch_bounds__(256)
void agg1_k(const __half* __restrict__ hfeat, const float* __restrict__ asrc,
            const float* __restrict__ adst, const int* __restrict__ cnt,
            const int* __restrict__ srcs, const float* __restrict__ b1,
            __half* __restrict__ out, int v0, int v1) {
    __shared__ float spq[8][4][40];
    __shared__ int   ssm[8][32];
    const float2* hf2 = reinterpret_cast<const float2*>(hfeat);

    int warp = (blockIdx.x * blockDim.x + threadIdx.x) >> 5;
    int wl   = (threadIdx.x >> 5);
    int lane = threadIdx.x & 31;
    int nw = (gridDim.x * blockDim.x) >> 5;
    int hsel = lane >> 3;
    float4 bb = reinterpret_cast<const float4*>(b1)[lane];

    for (int v = v0 + warp; v < v1; v += nw) {
        int deg = min(cnt[v], CAP);
        int s0 = v * CAP;
        float4 ad = reinterpret_cast<const float4*>(adst)[v];
        float den = 0.f;
        float4 acc = {0.f, 0.f, 0.f, 0.f};

        for (int base = 0; base < deg; base += 32) {
            int i = base + lane;
            float4 pv = {0.f, 0.f, 0.f, 0.f};
            int src = 0;
            if (i < deg) {
                src = srcs[s0 + i];
                float4 as = reinterpret_cast<const float4*>(asrc)[src];
                float e;
                e = as.x + ad.x; e = e > 0.f ? e : 0.2f * e; pv.x = __expf(e);
                e = as.y + ad.y; e = e > 0.f ? e : 0.2f * e; pv.y = __expf(e);
                e = as.z + ad.z; e = e > 0.f ? e : 0.2f * e; pv.z = __expf(e);
                e = as.w + ad.w; e = e > 0.f ? e : 0.2f * e; pv.w = __expf(e);
            }
            __syncwarp();                 // prior reads done before overwrite
            spq[wl][0][lane] = pv.x;
            spq[wl][1][lane] = pv.y;
            spq[wl][2][lane] = pv.z;
            spq[wl][3][lane] = pv.w;
            ssm[wl][lane] = src;
            __syncwarp();
            int c = min(32, deg - base);
            int j = 0;
            for (; j + 8 <= c; j += 8) {
                float4 qa = *reinterpret_cast<const float4*>(&spq[wl][hsel][j]);
                float4 qb = *reinterpret_cast<const float4*>(&spq[wl][hsel][j + 4]);
                int4   sa = *reinterpret_cast<const int4*>(&ssm[wl][j]);
                int4   sb = *reinterpret_cast<const int4*>(&ssm[wl][j + 4]);
                float qv[8] = {qa.x, qa.y, qa.z, qa.w, qb.x, qb.y, qb.z, qb.w};
                int   sv[8] = {sa.x, sa.y, sa.z, sa.w, sb.x, sb.y, sb.z, sb.w};
                float2 rw[8];
#pragma unroll
                for (int t = 0; t < 8; t++)
                    rw[t] = hf2[(size_t)sv[t] * 32 + lane];
#pragma unroll
                for (int t = 0; t < 8; t++) {
                    float2 fa = __half22float2(*reinterpret_cast<__half2*>(&rw[t].x));
                    float2 fb = __half22float2(*reinterpret_cast<__half2*>(&rw[t].y));
                    acc.x = fmaf(qv[t], fa.x, acc.x);
                    acc.y = fmaf(qv[t], fa.y, acc.y);
                    acc.z = fmaf(qv[t], fb.x, acc.z);
                    acc.w = fmaf(qv[t], fb.y, acc.w);
                    den += qv[t];
                }
            }
            for (; j < c; j++) {
                float q = spq[wl][hsel][j];
                int  sj = ssm[wl][j];
                float2 raw = hf2[(size_t)sj * 32 + lane];
                float2 fa = __half22float2(*reinterpret_cast<__half2*>(&raw.x));
                float2 fb = __half22float2(*reinterpret_cast<__half2*>(&raw.y));
                acc.x = fmaf(q, fa.x, acc.x);
                acc.y = fmaf(q, fa.y, acc.y);
                acc.z = fmaf(q, fb.x, acc.z);
                acc.w = fmaf(q, fb.y, acc.w);
                den += q;
            }
        }
        float rd = 1.f / (den + 1e-16f);
        uint2 ov;
        *reinterpret_cast<__half2*>(&ov.x) =
            __floats2half2_rn(fmaxf(acc.x * rd + bb.x, 0.f), fmaxf(acc.y * rd + bb.y, 0.f));
        *reinterpret_cast<__half2*>(&ov.y) =
            __floats2half2_rn(fmaxf(acc.z * rd + bb.z, 0.f), fmaxf(acc.w * rd + bb.w, 0.f));
        reinterpret_cast<uint2*>(out + (size_t)v * 128)[lane] = ov;
    }
}

// ---------------- layer2 aggregation (1 head, 64 ch), 8-wide batched ----------------
__global__ __launch_bounds__(256)
void agg2_k(const __half* __restrict__ hfeat, const float* __restrict__ asrc,
            const float* __restrict__ adst, const int* __restrict__ cnt,
            const int* __restrict__ srcs, const float* __restrict__ b2,
            float* __restrict__ out, int n) {
    __shared__ float2 sq[8][32];
    const __half2* hf2 = reinterpret_cast<const __half2*>(hfeat);

    int warp = (blockIdx.x * blockDim.x + threadIdx.x) >> 5;
    int wl   = (threadIdx.x >> 5);
    int lane = threadIdx.x & 31;
    int nw = (gridDim.x * blockDim.x) >> 5;
    float2 b = reinterpret_cast<const float2*>(b2)[lane];

    for (int v = warp; v < n; v += nw) {
        int deg = min(cnt[v], CAP);
        int s0 = v * CAP;
        float ad = adst[v];
        float den = 0.f;
        float2 a = {0.f, 0.f};

        for (int base = 0; base < deg; base += 32) {
            int i = base + lane;
            float p = 0.f;
            int src = 0;
            if (i < deg) {
                src = srcs[s0 + i];
                float e = asrc[src] + ad;
                e = e > 0.f ? e : 0.2f * e;
                p = __expf(e);
            }
            __syncwarp();
            sq[wl][lane] = make_float2(p, __int_as_float(src));
            __syncwarp();
            int c = min(32, deg - base);
            int j = 0;
            for (; j + 8 <= c; j += 8) {
                float qv[8]; int sv[8];
#pragma unroll
                for (int t = 0; t < 8; t++) {
                    float2 tt = sq[wl][j + t];
                    qv[t] = tt.x;
                    sv[t] = __float_as_int(tt.y);
                }
                __half2 hv[8];
#pragma unroll
                for (int t = 0; t < 8; t++)
                    hv[t] = hf2[(size_t)sv[t] * 32 + lane];
#pragma unroll
                for (int t = 0; t < 8; t++) {
                    float2 f = __half22float2(hv[t]);
                    a.x = fmaf(qv[t], f.x, a.x);
                    a.y = fmaf(qv[t], f.y, a.y);
                    den += qv[t];
                }
            }
            for (; j < c; j++) {
                float2 t = sq[wl][j];
                float q = t.x;
                int  sj = __float_as_int(t.y);
                float2 f = __half22float2(hf2[(size_t)sj * 32 + lane]);
                a.x = fmaf(q, f.x, a.x);
                a.y = fmaf(q, f.y, a.y);
                den += q;
            }
        }
        float rd = 1.f / (den + 1e-16f);
        float2 o;
        o.x = a.x * rd + b.x;
        o.y = a.y * rd + b.y;
        reinterpret_cast<float2*>(out + (size_t)v * 64)[lane] = o;
    }
}

// ---------------- launch ----------------
extern "C" void kernel_launch(void* const* d_in, const int* in_sizes, int n_in,
                              void* d_out, int out_size) {
    const float* x   = (const float*)d_in[0];
    const void*  ei  = d_in[1];
    const float* W1  = (const float*)d_in[2];
    const float* as1 = (const float*)d_in[3];
    const float* ad1 = (const float*)d_in[4];
    const float* b1  = (const float*)d_in[5];
    const float* W2  = (const float*)d_in[6];
    const float* as2 = (const float*)d_in[7];
    const float* ad2 = (const float*)d_in[8];
    const float* b2  = (const float*)d_in[9];
    float* out = (float*)d_out;

    int n = in_sizes[0] / 128;           // 50000
    long long E = in_sizes[1] / 2;       // 1600000

    __half *p_h1h, *p_l1h, *p_h2h;
    float *p_as1, *p_ad1, *p_as2, *p_ad2;
    int *p_cnt, *p_srcs;
    cudaGetSymbolAddress((void**)&p_h1h, g_h1h);
    cudaGetSymbolAddress((void**)&p_l1h, g_l1h);
    cudaGetSymbolAddress((void**)&p_h2h, g_h2h);
    cudaGetSymbolAddress((void**)&p_as1, g_as1);
    cudaGetSymbolAddress((void**)&p_ad1, g_ad1);
    cudaGetSymbolAddress((void**)&p_as2, g_as2);
    cudaGetSymbolAddress((void**)&p_ad2, g_ad2);
    cudaGetSymbolAddress((void**)&p_cnt, g_cnt);
    cudaGetSymbolAddress((void**)&p_srcs, g_srcs);

    int gemm_blocks = (n + 127) / 128;               // 391
    int half_blocks = gemm_blocks / 2;               // 195
    int vsplit = half_blocks * 128;                  // 24960 (node/row split)

    cudaStream_t s2;
    cudaEvent_t ev1, ev2, evA0, evA1, evG;
    cudaStreamCreateWithFlags(&s2, cudaStreamNonBlocking);
    cudaEventCreateWithFlags(&ev1, cudaEventDisableTiming);
    cudaEventCreateWithFlags(&ev2, cudaEventDisableTiming);
    cudaEventCreateWithFlags(&evA0, cudaEventDisableTiming);
    cudaEventCreateWithFlags(&evA1, cudaEventDisableTiming);
    cudaEventCreateWithFlags(&evG, cudaEventDisableTiming);

    cudaEventRecord(ev1, 0);
    cudaStreamWaitEvent(s2, ev1, 0);

    // side stream: CSR build
    init_k<<<(n + 255) / 256, 256, 0, s2>>>(ei, n, p_cnt);
    scat_k<<<2048, 256, 0, s2>>>(ei, E, n, p_cnt, p_srcs);
    cudaEventRecord(ev2, s2);

    // main stream: gemm1 + fused alpha1
    gemm1_k<<<gemm_blocks, 256>>>(x, W1, as1, ad1, p_h1h, p_as1, p_ad1, n);

    // join, then chunked agg1 / gemm2 pipeline
    cudaStreamWaitEvent(0, ev2, 0);
    int wb0 = (vsplit * 32 + 255) / 256;
    int wb1 = ((n - vsplit) * 32 + 255) / 256;
    agg1_k<<<wb0, 256>>>(p_h1h, p_as1, p_ad1, p_cnt, p_srcs, b1, p_l1h, 0, vsplit);
    cudaEventRecord(evA0, 0);
    agg1_k<<<wb1, 256>>>(p_h1h, p_as1, p_ad1, p_cnt, p_srcs, b1, p_l1h, vsplit, n);
    cudaEventRecord(evA1, 0);

    // gemm2 chunk0 overlaps agg1 chunk1 on the side stream
    cudaStreamWaitEvent(s2, evA0, 0);
    gemm2_k<<<half_blocks, 256, 0, s2>>>(p_l1h, W2, as2, ad2, p_h2h, p_as2, p_ad2, n, 0);
    cudaStreamWaitEvent(s2, evA1, 0);
    gemm2_k<<<gemm_blocks - half_blocks, 256, 0, s2>>>(p_l1h, W2, as2, ad2, p_h2h,
                                                       p_as2, p_ad2, n, vsplit);
    cudaEventRecord(evG, s2);

    cudaStreamWaitEvent(0, evG, 0);
    int warp_blocks = (n * 32 + 255) / 256;
    agg2_k<<<warp_blocks, 256>>>(p_h2h, p_as2, p_ad2, p_cnt, p_srcs, b2, out, n);
}

// round 15
// speedup vs baseline: 1.8962x; 1.1161x over previous
#include <cuda_runtime.h>
#include <cuda_fp16.h>
#include <mma.h>
#include <math.h>

using namespace nvcuda;

#define FULL 0xffffffffu

static const int NMAX = 50000;
static const int NPAD = 50048;          // 391 * 128
static const int CAP  = 192;            // bucket capacity (Poisson(32) tail ~1e-100)
static const long long EMAX = 1600000;

// ---------------- scratch (static __device__ — no allocation) ----------------
__device__ __align__(32) __half g_h1h[NPAD * 128];
__device__ __align__(32) __half g_l1h[NPAD * 128];
__device__ __align__(32) __half g_h2h[NPAD * 64];
__device__ __align__(16) float g_as1[NMAX * 4];
__device__ __align__(16) float g_ad1[NMAX * 4];
__device__ float g_as2[NMAX];
__device__ float g_ad2[NMAX];
__device__ int   g_cnt[NMAX];
__device__ int   g_srcs[NMAX * CAP];
__device__ int   g_is64;

// ---------------- init: zero counters + edge dtype detection ----------------
__global__ void init_k(const void* ei, int n, int* __restrict__ cnt) {
    int i = blockIdx.x * blockDim.x + threadIdx.x;
    if (i < n) cnt[i] = 0;
    if (blockIdx.x == 0 && threadIdx.x == 0) {
        const long long* p = (const long long*)ei;
        int ok = 1;
        for (int k = 0; k < 64; k++) {
            long long v = p[k];
            if (v < 0 || v >= (long long)n) { ok = 0; break; }
        }
        g_is64 = ok;
    }
}

__device__ __forceinline__ int edge_src(const void* ei, long long E, long long i) {
    return g_is64 ? (int)((const long long*)ei)[i] : ((const int*)ei)[i];
}
__device__ __forceinline__ int edge_dst(const void* ei, long long E, long long i) {
    return g_is64 ? (int)((const long long*)ei)[E + i] : ((const int*)ei)[E + i];
}

// ---------------- one-pass bucket scatter ----------------
__global__ void scat_k(const void* ei, long long E, int n, int* __restrict__ cnt,
                       int* __restrict__ srcs) {
    long long total = E + n;
    for (long long i = (long long)blockIdx.x * blockDim.x + threadIdx.x; i < total;
         i += (long long)gridDim.x * blockDim.x) {
        int s, d;
        if (i < E) { s = edge_src(ei, E, i); d = edge_dst(ei, E, i); }
        else { s = d = (int)(i - E); }
        int pos = atomicAdd(&cnt[d], 1);
        if (pos < CAP) srcs[d * CAP + pos] = s;
    }
}

// ---------------- GEMM1 (wmma) + fused alpha1 ----------------
__global__ __launch_bounds__(256)
void gemm1_k(const float* __restrict__ A, const float* __restrict__ W,
             const float* __restrict__ a_src, const float* __restrict__ a_dst,
             __half* __restrict__ Ch, float* __restrict__ asrc,
             float* __restrict__ adst, int n) {
    __shared__ __half As[2][128][48];
    __shared__ __half Bs[2][32][144];

    int tid = threadIdx.x;
    int wid = tid >> 5, lane = tid & 31;
    int wm = wid >> 2, wn = wid & 3;
    int row0 = blockIdx.x * 128;

    float4 va[4], vw[4];
    auto fetch = [&](int kc) {
#pragma unroll
        for (int q = 0; q < 4; q++) {
            int f = tid + q * 256;
            int r = f >> 3, c4 = f & 7;
            int gr = row0 + r;
            va[q] = (gr < n) ? *reinterpret_cast<const float4*>(&A[(size_t)gr * 128 + kc + c4 * 4])
                             : make_float4(0.f, 0.f, 0.f, 0.f);
        }
#pragma unroll
        for (int q = 0; q < 4; q++) {
            int f = tid + q * 256;
            int r = f >> 5, c4 = f & 31;
            vw[q] = *reinterpret_cast<const float4*>(&W[(size_t)(kc + r) * 128 + c4 * 4]);
        }
    };
    auto store = [&](int b) {
#pragma unroll
        for (int q = 0; q < 4; q++) {
            int f = tid + q * 256;
            int r = f >> 3, c = (f & 7) * 4;
            *reinterpret_cast<__half2*>(&As[b][r][c])     = __floats2half2_rn(va[q].x, va[q].y);
            *reinterpret_cast<__half2*>(&As[b][r][c + 2]) = __floats2half2_rn(va[q].z, va[q].w);
        }
#pragma unroll
        for (int q = 0; q < 4; q++) {
            int f = tid + q * 256;
            int r = f >> 5, c = (f & 31) * 4;
            *reinterpret_cast<__half2*>(&Bs[b][r][c])     = __floats2half2_rn(vw[q].x, vw[q].y);
            *reinterpret_cast<__half2*>(&Bs[b][r][c + 2]) = __floats2half2_rn(vw[q].z, vw[q].w);
        }
    };

    wmma::fragment<wmma::accumulator, 16, 16, 16, float> cf[4][2];
#pragma unroll
    for (int i = 0; i < 4; i++)
#pragma unroll
        for (int j = 0; j < 2; j++) wmma::fill_fragment(cf[i][j], 0.f);

    fetch(0); store(0); __syncthreads();

#pragma unroll
    for (int it = 0; it < 4; it++) {
        int b = it & 1;
        if (it < 3) fetch((it + 1) * 32);
#pragma unroll
        for (int kk = 0; kk < 32; kk += 16) {
            wmma::fragment<wmma::matrix_a, 16, 16, 16, __half, wmma::row_major> af[4];
            wmma::fragment<wmma::matrix_b, 16, 16, 16, __half, wmma::row_major> bf[2];
#pragma unroll
            for (int i = 0; i < 4; i++)
                wmma::load_matrix_sync(af[i], &As[b][wm * 64 + i * 16][kk], 48);
#pragma unroll
            for (int j = 0; j < 2; j++)
                wmma::load_matrix_sync(bf[j], &Bs[b][kk][wn * 32 + j * 16], 144);
#pragma unroll
            for (int i = 0; i < 4; i++)
#pragma unroll
                for (int j = 0; j < 2; j++)
                    wmma::mma_sync(cf[i][j], af[i], bf[j], cf[i][j]);
        }
        if (it < 3) store(b ^ 1);
        __syncthreads();
    }

    float (*cs)[16][20] = reinterpret_cast<float (*)[16][20]>(&As[0][0][0]);
    int r = lane >> 1, hh = lane & 1;
#pragma unroll
    for (int i = 0; i < 4; i++) {
        float asum = 0.f, dsum = 0.f;
#pragma unroll
        for (int j = 0; j < 2; j++) {
            wmma::store_matrix_sync(&cs[wid][0][0], cf[i][j], 20, wmma::mem_row_major);
            __syncwarp();
            const float* rp = &cs[wid][r][hh * 8];
            __half2 o[4];
#pragma unroll
            for (int t = 0; t < 4; t++) {
                float w0 = rp[2 * t], w1 = rp[2 * t + 1];
                o[t] = __floats2half2_rn(w0, w1);
                int c = wn * 32 + j * 16 + hh * 8 + 2 * t;
                asum += w0 * __ldg(&a_src[c]) + w1 * __ldg(&a_src[c + 1]);
                dsum += w0 * __ldg(&a_dst[c]) + w1 * __ldg(&a_dst[c + 1]);
            }
            *reinterpret_cast<uint4*>(
                &Ch[(size_t)(row0 + wm * 64 + i * 16 + r) * 128 + wn * 32 + j * 16 + hh * 8]) =
                *reinterpret_cast<uint4*>(o);
            __syncwarp();
        }
        asum += __shfl_xor_sync(FULL, asum, 1);
        dsum += __shfl_xor_sync(FULL, dsum, 1);
        int gr = row0 + wm * 64 + i * 16 + r;
        if (hh == 0 && gr < n) {
            asrc[gr * 4 + wn] = asum;
            adst[gr * 4 + wn] = dsum;
        }
    }
}

// ---------------- GEMM2 (wmma) + fused alpha2 (row-chunked) ----------------
__global__ __launch_bounds__(256)
void gemm2_k(const __half* __restrict__ Ah, const float* __restrict__ W,
             const float* __restrict__ a_src, const float* __restrict__ a_dst,
             __half* __restrict__ Ch, float* __restrict__ asrc,
             float* __restrict__ adst, int n, int rowbase) {
    __shared__ __half As[2][128][48];
    __shared__ __half Bs[2][32][80];
    __shared__ float spa[128][2], spd[128][2];

    int tid = threadIdx.x;
    int wid = tid >> 5, lane = tid & 31;
    int wm = wid >> 1, wn = wid & 1;
    int row0 = rowbase + blockIdx.x * 128;

    uint2 va[4]; float4 vw[2];
    auto fetch = [&](int kc) {
#pragma unroll
        for (int q = 0; q < 4; q++) {
            int f = tid + q * 256;
            int r = f >> 3, c4 = f & 7;
            int gr = row0 + r;
            va[q] = (gr < n) ? *reinterpret_cast<const uint2*>(&Ah[(size_t)gr * 128 + kc + c4 * 4])
                             : make_uint2(0u, 0u);
        }
#pragma unroll
        for (int q = 0; q < 2; q++) {
            int f = tid + q * 256;
            int r = f >> 4, c4 = f & 15;
            vw[q] = *reinterpret_cast<const float4*>(&W[(size_t)(kc + r) * 64 + c4 * 4]);
        }
    };
    auto store = [&](int b) {
#pragma unroll
        for (int q = 0; q < 4; q++) {
            int f = tid + q * 256;
            int r = f >> 3, c = (f & 7) * 4;
            *reinterpret_cast<uint2*>(&As[b][r][c]) = va[q];
        }
#pragma unroll
        for (int q = 0; q < 2; q++) {
            int f = tid + q * 256;
            int r = f >> 4, c = (f & 15) * 4;
            *reinterpret_cast<__half2*>(&Bs[b][r][c])     = __floats2half2_rn(vw[q].x, vw[q].y);
            *reinterpret_cast<__half2*>(&Bs[b][r][c + 2]) = __floats2half2_rn(vw[q].z, vw[q].w);
        }
    };

    wmma::fragment<wmma::accumulator, 16, 16, 16, float> cf[2][2];
#pragma unroll
    for (int i = 0; i < 2; i++)
#pragma unroll
        for (int j = 0; j < 2; j++) wmma::fill_fragment(cf[i][j], 0.f);

    fetch(0); store(0); __syncthreads();

#pragma unroll
    for (int it = 0; it < 4; it++) {
        int b = it & 1;
        if (it < 3) fetch((it + 1) * 32);
#pragma unroll
        for (int kk = 0; kk < 32; kk += 16) {
            wmma::fragment<wmma::matrix_a, 16, 16, 16, __half, wmma::row_major> af[2];
            wmma::fragment<wmma::matrix_b, 16, 16, 16, __half, wmma::row_major> bf[2];
#pragma unroll
            for (int i = 0; i < 2; i++)
                wmma::load_matrix_sync(af[i], &As[b][wm * 32 + i * 16][kk], 48);
#pragma unroll
            for (int j = 0; j < 2; j++)
                wmma::load_matrix_sync(bf[j], &Bs[b][kk][wn * 32 + j * 16], 80);
#pragma unroll
            for (int i = 0; i < 2; i++)
#pragma unroll
                for (int j = 0; j < 2; j++)
                    wmma::mma_sync(cf[i][j], af[i], bf[j], cf[i][j]);
        }
        if (it < 3) store(b ^ 1);
        __syncthreads();
    }

    float (*cs)[16][20] = reinterpret_cast<float (*)[16][20]>(&As[0][0][0]);
    int r = lane >> 1, hh = lane & 1;
#pragma unroll
    for (int i = 0; i < 2; i++) {
        float asum = 0.f, dsum = 0.f;
#pragma unroll
        for (int j = 0; j < 2; j++) {
            wmma::store_matrix_sync(&cs[wid][0][0], cf[i][j], 20, wmma::mem_row_major);
            __syncwarp();
            const float* rp = &cs[wid][r][hh * 8];
            __half2 o[4];
#pragma unroll
            for (int t = 0; t < 4; t++) {
                float w0 = rp[2 * t], w1 = rp[2 * t + 1];
                o[t] = __floats2half2_rn(w0, w1);
                int c = wn * 32 + j * 16 + hh * 8 + 2 * t;
                asum += w0 * __ldg(&a_src[c]) + w1 * __ldg(&a_src[c + 1]);
                dsum += w0 * __ldg(&a_dst[c]) + w1 * __ldg(&a_dst[c + 1]);
            }
            *reinterpret_cast<uint4*>(
                &Ch[(size_t)(row0 + wm * 32 + i * 16 + r) * 64 + wn * 32 + j * 16 + hh * 8]) =
                *reinterpret_cast<uint4*>(o);
            __syncwarp();
        }
        asum += __shfl_xor_sync(FULL, asum, 1);
        dsum += __shfl_xor_sync(FULL, dsum, 1);
        int lr = wm * 32 + i * 16 + r;
        if (hh == 0) { spa[lr][wn] = asum; spd[lr][wn] = dsum; }
    }
    __syncthreads();
    if (tid < 128) {
        int gr = row0 + tid;
        if (gr < n) {
            asrc[gr] = spa[tid][0] + spa[tid][1];
            adst[gr] = spd[tid][0] + spd[tid][1];
        }
    }
}

// ---------------- layer1 aggregation: warp per dst (R12-proven structure) ----------
__global__ __launch_bounds__(256)
void agg1_k(const __half* __restrict__ hfeat, const float* __restrict__ asrc,
            const float* __restrict__ adst, const int* __restrict__ cnt,
            const int* __restrict__ srcs, const float* __restrict__ b1,
            __half* __restrict__ out, int v0, int v1) {
    __shared__ float4 spm[8][32];
    __shared__ int    ssm[8][32];
    float* spf = reinterpret_cast<float*>(spm);
    const float2* hf2 = reinterpret_cast<const float2*>(hfeat);

    int warp = (blockIdx.x * blockDim.x + threadIdx.x) >> 5;
    int wl   = (threadIdx.x >> 5);
    int lane = threadIdx.x & 31;
    int nw = (gridDim.x * blockDim.x) >> 5;
    int hsel = lane >> 3;
    float4 bb = reinterpret_cast<const float4*>(b1)[lane];

    for (int v = v0 + warp; v < v1; v += nw) {
        int deg = min(cnt[v], CAP);
        int s0 = v * CAP;
        float4 ad = reinterpret_cast<const float4*>(adst)[v];
        float den = 0.f;
        float4 acc = {0.f, 0.f, 0.f, 0.f};

        for (int base = 0; base < deg; base += 32) {
            int i = base + lane;
            float4 pv = {0.f, 0.f, 0.f, 0.f};
            int src = 0;
            if (i < deg) {
                src = srcs[s0 + i];
                float4 as = reinterpret_cast<const float4*>(asrc)[src];
                float e;
                e = as.x + ad.x; e = e > 0.f ? e : 0.2f * e; pv.x = __expf(e);
                e = as.y + ad.y; e = e > 0.f ? e : 0.2f * e; pv.y = __expf(e);
                e = as.z + ad.z; e = e > 0.f ? e : 0.2f * e; pv.z = __expf(e);
                e = as.w + ad.w; e = e > 0.f ? e : 0.2f * e; pv.w = __expf(e);
            }
            __syncwarp();                 // prior reads done before overwrite
            spm[wl][lane] = pv;
            ssm[wl][lane] = src;
            __syncwarp();
            int c = min(32, deg - base);
            int j = 0;
            for (; j + 8 <= c; j += 8) {
                float  qv[8];
                int    sv[8];
#pragma unroll
                for (int t = 0; t < 8; t++) {
                    qv[t] = spf[(wl << 7) + ((j + t) << 2) + hsel];
                    sv[t] = ssm[wl][j + t];
                }
                float2 rw[8];
#pragma unroll
                for (int t = 0; t < 8; t++)
                    rw[t] = hf2[(size_t)sv[t] * 32 + lane];
#pragma unroll
                for (int t = 0; t < 8; t++) {
                    float2 fa = __half22float2(*reinterpret_cast<__half2*>(&rw[t].x));
                    float2 fb = __half22float2(*reinterpret_cast<__half2*>(&rw[t].y));
                    acc.x = fmaf(qv[t], fa.x, acc.x);
                    acc.y = fmaf(qv[t], fa.y, acc.y);
                    acc.z = fmaf(qv[t], fb.x, acc.z);
                    acc.w = fmaf(qv[t], fb.y, acc.w);
                    den += qv[t];
                }
            }
            for (; j < c; j++) {
                float q = spf[(wl << 7) + (j << 2) + hsel];
                int  sj = ssm[wl][j];
                float2 raw = hf2[(size_t)sj * 32 + lane];
                float2 fa = __half22float2(*reinterpret_cast<__half2*>(&raw.x));
                float2 fb = __half22float2(*reinterpret_cast<__half2*>(&raw.y));
                acc.x = fmaf(q, fa.x, acc.x);
                acc.y = fmaf(q, fa.y, acc.y);
                acc.z = fmaf(q, fb.x, acc.z);
                acc.w = fmaf(q, fb.y, acc.w);
                den += q;
            }
        }
        float rd = 1.f / (den + 1e-16f);
        uint2 ov;
        *reinterpret_cast<__half2*>(&ov.x) =
            __floats2half2_rn(fmaxf(acc.x * rd + bb.x, 0.f), fmaxf(acc.y * rd + bb.y, 0.f));
        *reinterpret_cast<__half2*>(&ov.y) =
            __floats2half2_rn(fmaxf(acc.z * rd + bb.z, 0.f), fmaxf(acc.w * rd + bb.w, 0.f));
        reinterpret_cast<uint2*>(out + (size_t)v * 128)[lane] = ov;
    }
}

// ---------------- layer2 aggregation (1 head, 64 ch), 8-wide batched ----------------
__global__ __launch_bounds__(256)
void agg2_k(const __half* __restrict__ hfeat, const float* __restrict__ asrc,
            const float* __restrict__ adst, const int* __restrict__ cnt,
            const int* __restrict__ srcs, const float* __restrict__ b2,
            float* __restrict__ out, int n) {
    __shared__ float2 sq[8][32];
    const __half2* hf2 = reinterpret_cast<const __half2*>(hfeat);

    int warp = (blockIdx.x * blockDim.x + threadIdx.x) >> 5;
    int wl   = (threadIdx.x >> 5);
    int lane = threadIdx.x & 31;
    int nw = (gridDim.x * blockDim.x) >> 5;
    float2 b = reinterpret_cast<const float2*>(b2)[lane];

    for (int v = warp; v < n; v += nw) {
        int deg = min(cnt[v], CAP);
        int s0 = v * CAP;
        float ad = adst[v];
        float den = 0.f;
        float2 a = {0.f, 0.f};

        for (int base = 0; base < deg; base += 32) {
            int i = base + lane;
            float p = 0.f;
            int src = 0;
            if (i < deg) {
                src = srcs[s0 + i];
                float e = asrc[src] + ad;
                e = e > 0.f ? e : 0.2f * e;
                p = __expf(e);
            }
            __syncwarp();
            sq[wl][lane] = make_float2(p, __int_as_float(src));
            __syncwarp();
            int c = min(32, deg - base);
            int j = 0;
            for (; j + 8 <= c; j += 8) {
                float qv[8]; int sv[8];
#pragma unroll
                for (int t = 0; t < 8; t++) {
                    float2 tt = sq[wl][j + t];
                    qv[t] = tt.x;
                    sv[t] = __float_as_int(tt.y);
                }
                __half2 hv[8];
#pragma unroll
                for (int t = 0; t < 8; t++)
                    hv[t] = hf2[(size_t)sv[t] * 32 + lane];
#pragma unroll
                for (int t = 0; t < 8; t++) {
                    float2 f = __half22float2(hv[t]);
                    a.x = fmaf(qv[t], f.x, a.x);
                    a.y = fmaf(qv[t], f.y, a.y);
                    den += qv[t];
                }
            }
            for (; j < c; j++) {
                float2 t = sq[wl][j];
                float q = t.x;
                int  sj = __float_as_int(t.y);
                float2 f = __half22float2(hf2[(size_t)sj * 32 + lane]);
                a.x = fmaf(q, f.x, a.x);
                a.y = fmaf(q, f.y, a.y);
                den += q;
            }
        }
        float rd = 1.f / (den + 1e-16f);
        float2 o;
        o.x = a.x * rd + b.x;
        o.y = a.y * rd + b.y;
        reinterpret_cast<float2*>(out + (size_t)v * 64)[lane] = o;
    }
}

// ---------------- launch ----------------
extern "C" void kernel_launch(void* const* d_in, const int* in_sizes, int n_in,
                              void* d_out, int out_size) {
    const float* x   = (const float*)d_in[0];
    const void*  ei  = d_in[1];
    const float* W1  = (const float*)d_in[2];
    const float* as1 = (const float*)d_in[3];
    const float* ad1 = (const float*)d_in[4];
    const float* b1  = (const float*)d_in[5];
    const float* W2  = (const float*)d_in[6];
    const float* as2 = (const float*)d_in[7];
    const float* ad2 = (const float*)d_in[8];
    const float* b2  = (const float*)d_in[9];
    float* out = (float*)d_out;

    int n = in_sizes[0] / 128;           // 50000
    long long E = in_sizes[1] / 2;       // 1600000

    __half *p_h1h, *p_l1h, *p_h2h;
    float *p_as1, *p_ad1, *p_as2, *p_ad2;
    int *p_cnt, *p_srcs;
    cudaGetSymbolAddress((void**)&p_h1h, g_h1h);
    cudaGetSymbolAddress((void**)&p_l1h, g_l1h);
    cudaGetSymbolAddress((void**)&p_h2h, g_h2h);
    cudaGetSymbolAddress((void**)&p_as1, g_as1);
    cudaGetSymbolAddress((void**)&p_ad1, g_ad1);
    cudaGetSymbolAddress((void**)&p_as2, g_as2);
    cudaGetSymbolAddress((void**)&p_ad2, g_ad2);
    cudaGetSymbolAddress((void**)&p_cnt, g_cnt);
    cudaGetSymbolAddress((void**)&p_srcs, g_srcs);

    int gemm_blocks = (n + 127) / 128;               // 391
    int half_blocks = gemm_blocks / 2;               // 195
    int vsplit = half_blocks * 128;                  // 24960 (node/row split)

    cudaStream_t s2;
    cudaEvent_t ev1, ev2, evA0, evA1, evG;
    cudaStreamCreateWithFlags(&s2, cudaStreamNonBlocking);
    cudaEventCreateWithFlags(&ev1, cudaEventDisableTiming);
    cudaEventCreateWithFlags(&ev2, cudaEventDisableTiming);
    cudaEventCreateWithFlags(&evA0, cudaEventDisableTiming);
    cudaEventCreateWithFlags(&evA1, cudaEventDisableTiming);
    cudaEventCreateWithFlags(&evG, cudaEventDisableTiming);

    cudaEventRecord(ev1, 0);
    cudaStreamWaitEvent(s2, ev1, 0);

    // side stream: CSR build
    init_k<<<(n + 255) / 256, 256, 0, s2>>>(ei, n, p_cnt);
    scat_k<<<2048, 256, 0, s2>>>(ei, E, n, p_cnt, p_srcs);
    cudaEventRecord(ev2, s2);

    // main stream: gemm1 + fused alpha1
    gemm1_k<<<gemm_blocks, 256>>>(x, W1, as1, ad1, p_h1h, p_as1, p_ad1, n);

    // join, then chunked agg1 / gemm2 pipeline
    cudaStreamWaitEvent(0, ev2, 0);
    int wb0 = (vsplit * 32 + 255) / 256;
    int wb1 = ((n - vsplit) * 32 + 255) / 256;
    agg1_k<<<wb0, 256>>>(p_h1h, p_as1, p_ad1, p_cnt, p_srcs, b1, p_l1h, 0, vsplit);
    cudaEventRecord(evA0, 0);
    agg1_k<<<wb1, 256>>>(p_h1h, p_as1, p_ad1, p_cnt, p_srcs, b1, p_l1h, vsplit, n);
    cudaEventRecord(evA1, 0);

    // gemm2 chunk0 overlaps agg1 chunk1 on the side stream
    cudaStreamWaitEvent(s2, evA0, 0);
    gemm2_k<<<half_blocks, 256, 0, s2>>>(p_l1h, W2, as2, ad2, p_h2h, p_as2, p_ad2, n, 0);
    cudaStreamWaitEvent(s2, evA1, 0);
    gemm2_k<<<gemm_blocks - half_blocks, 256, 0, s2>>>(p_l1h, W2, as2, ad2, p_h2h,
                                                       p_as2, p_ad2, n, vsplit);
    cudaEventRecord(evG, s2);

    cudaStreamWaitEvent(0, evG, 0);
    int warp_blocks = (n * 32 + 255) / 256;
    agg2_k<<<warp_blocks, 256>>>(p_h2h, p_as2, p_ad2, p_cnt, p_srcs, b2, out, n);
}